// round 6
// baseline (speedup 1.0000x reference)
#include <cuda_runtime.h>

// IF spiking neuron forward:
//   mem0 = dtmem * thresh
//   for t: mem += x_t; spike = (mem >= thresh) ? thresh : 0; mem -= spike
//
// Mapping: TWO feature-vec4 sites per thread (f and f+256), all 8 x-loads
// front-batched -> per-warp MLP~10 to push LDG into the issue-floor regime.
// grid.x = B (fast launch dim: blocks sharing a feature chunk's params
// launch adjacently -> param reads L2-served). Default cache policy (.cs
// measured ~6% BW penalty on sm_103a in R2-R4).

#define T_STEPS 4

__global__ __launch_bounds__(256) void if_fwd_kernel(
    const float4* __restrict__ x,      // [T, B, feat_v]
    const float4* __restrict__ thresh, // [feat_v]
    const float4* __restrict__ dtmem,  // [feat_v]
    float4* __restrict__ out,          // [T, B, feat_v]
    int feat_v,                        // 1024*3072/4
    int n_per_t_v)                     // B*feat_v (t-stride in vec4)
{
    // Each block covers 2*blockDim consecutive vec4 features.
    int f0 = blockIdx.y * (blockDim.x * 2) + threadIdx.x;
    int f1 = f0 + blockDim.x;
    int b  = blockIdx.x;

    long long baseA = (long long)b * feat_v + f0;
    long long baseB = (long long)b * feat_v + f1;

    // Front-batch all 8 independent time-step loads (MLP=8) + params.
    float4 a0 = __ldg(&x[baseA]);
    float4 a1 = __ldg(&x[baseA + (long long)n_per_t_v]);
    float4 a2 = __ldg(&x[baseA + 2LL * n_per_t_v]);
    float4 a3 = __ldg(&x[baseA + 3LL * n_per_t_v]);
    float4 b0 = __ldg(&x[baseB]);
    float4 b1 = __ldg(&x[baseB + (long long)n_per_t_v]);
    float4 b2 = __ldg(&x[baseB + 2LL * n_per_t_v]);
    float4 b3 = __ldg(&x[baseB + 3LL * n_per_t_v]);

    float4 thA = __ldg(&thresh[f0]);
    float4 dmA = __ldg(&dtmem[f0]);
    float4 thB = __ldg(&thresh[f1]);
    float4 dmB = __ldg(&dtmem[f1]);

    float4 memA, memB, sp;
    memA.x = dmA.x * thA.x; memA.y = dmA.y * thA.y;
    memA.z = dmA.z * thA.z; memA.w = dmA.w * thA.w;
    memB.x = dmB.x * thB.x; memB.y = dmB.y * thB.y;
    memB.z = dmB.z * thB.z; memB.w = dmB.w * thB.w;

#define STEP(mem, th, xv, base, tidx)                                       \
    mem.x += xv.x; sp.x = (mem.x >= th.x) ? th.x : 0.0f; mem.x -= sp.x;     \
    mem.y += xv.y; sp.y = (mem.y >= th.y) ? th.y : 0.0f; mem.y -= sp.y;     \
    mem.z += xv.z; sp.z = (mem.z >= th.z) ? th.z : 0.0f; mem.z -= sp.z;     \
    mem.w += xv.w; sp.w = (mem.w >= th.w) ? th.w : 0.0f; mem.w -= sp.w;     \
    out[base + (long long)(tidx) * n_per_t_v] = sp;

    // Interleave the two independent chains (hides FADD latency, frees
    // each x-register right after use).
    STEP(memA, thA, a0, baseA, 0)
    STEP(memB, thB, b0, baseB, 0)
    STEP(memA, thA, a1, baseA, 1)
    STEP(memB, thB, b1, baseB, 1)
    STEP(memA, thA, a2, baseA, 2)
    STEP(memB, thB, b2, baseB, 2)
    STEP(memA, thA, a3, baseA, 3)
    STEP(memB, thB, b3, baseB, 3)
#undef STEP
}

extern "C" void kernel_launch(void* const* d_in, const int* in_sizes, int n_in,
                              void* d_out, int out_size) {
    const float* x      = (const float*)d_in[0];
    const float* thresh = (const float*)d_in[1];
    const float* dtmem  = (const float*)d_in[2];
    float* out          = (float*)d_out;

    int total  = in_sizes[0];           // T*B*1024*3072
    int feat_n = in_sizes[1];           // 1024*3072
    int B      = total / (T_STEPS * feat_n);

    int feat_v    = feat_n / 4;         // 786432, divisible by 512
    int n_per_t_v = B * feat_v;

    int threads = 256;
    int fchunks = feat_v / (threads * 2);   // 1536
    dim3 grid(B, fchunks);

    if_fwd_kernel<<<grid, threads>>>(
        (const float4*)x, (const float4*)thresh, (const float4*)dtmem,
        (float4*)out, feat_v, n_per_t_v);
}